// round 16
// baseline (speedup 1.0000x reference)
#include <cuda_runtime.h>
#include <cuda_bf16.h>
#include <math.h>
#include <stdint.h>

#define F_DIM 256
#define N_MAX 200000
#define B_MAX 4000
#define NPAD (N_MAX + 128)

// ---- scratch (device globals: allocation-free) ----
__device__ float g_kq[B_MAX * F_DIM];
__device__ float g_kb[B_MAX];
__device__ float g_vmol[B_MAX * F_DIM];
__device__ float g_a[N_MAX];
__device__ float g_part[(N_MAX + 7) / 8];
__device__ float g_inv[1];
__device__ int   g_ctrA, g_ctrB, g_ctrC;
__device__ int   g_flagA, g_flagB;
__device__ float g_H[(size_t)NPAD * F_DIM];
// ping-pong tf32 A operand buffers (stage parity)
__device__ float g_A0[(size_t)NPAD * F_DIM];
__device__ float g_A1[(size_t)NPAD * F_DIM];
__device__ float g_Wt[5 * F_DIM * F_DIM];   // tf32-rounded weights

// ============================================================
// helpers
// ============================================================
__device__ __forceinline__ uint32_t smem_u32(const void* p) {
    uint32_t a;
    asm("{ .reg .u64 t; cvta.to.shared.u64 t, %1; cvt.u32.u64 %0, t; }" : "=r"(a) : "l"(p));
    return a;
}
#define LDSM_X4(r, addr) \
    asm volatile("ldmatrix.sync.aligned.m8n8.x4.shared.b16 {%0,%1,%2,%3}, [%4];" \
        : "=r"((r)[0]), "=r"((r)[1]), "=r"((r)[2]), "=r"((r)[3]) : "r"(addr))
#define MMA_TF32(c, a, b) \
    asm volatile("mma.sync.aligned.m16n8k8.row.col.f32.tf32.tf32.f32 " \
        "{%0,%1,%2,%3}, {%4,%5,%6,%7}, {%8,%9}, {%0,%1,%2,%3};" \
        : "+f"((c)[0]), "+f"((c)[1]), "+f"((c)[2]), "+f"((c)[3]) \
        : "r"((a)[0]), "r"((a)[1]), "r"((a)[2]), "r"((a)[3]), "r"((b)[0]), "r"((b)[1]))
#define CP_ASYNC16(dst, src) \
    asm volatile("cp.async.cg.shared.global [%0], [%1], 16;" :: "r"(dst), "l"(src))
#define CP_COMMIT() asm volatile("cp.async.commit_group;" ::: "memory")
#define CP_WAIT0()  asm volatile("cp.async.wait_group 0;" ::: "memory")
#define CP_WAIT1()  asm volatile("cp.async.wait_group 1;" ::: "memory")

__device__ __forceinline__ float tf32r(float x) {
    uint32_t u;
    asm("cvt.rna.tf32.f32 %0, %1;" : "=r"(u) : "f"(x));
    return __uint_as_float(u);
}
__device__ __forceinline__ float swtf(float v, float al, float be) {
    float s  = be * v;
    float sw = al * s * (1.f / (1.f + __expf(-s)));
    return tf32r(sw);
}

// ============================================================
// K1: fused frontend. Grid = [mol (molB)] + [weights (wB)] + [scores (gS)]
//     + [xform (xB)]. Phase gating via flags; dispatch order (lower bid
//     first) guarantees spinners never starve their producers.
// ============================================================
__global__ void __launch_bounds__(256) frontend(
    const float* __restrict__ E,  const float* __restrict__ Wq,
    const float* __restrict__ bq, const float* __restrict__ Wk,
    const float* __restrict__ Wv, const float* __restrict__ x,
    const int* __restrict__ idx,
    const float* __restrict__ W1, const float* __restrict__ W2,
    const float* __restrict__ Wout,
    const float* __restrict__ a1, const float* __restrict__ b1,
    int B, int N, int R, int molB, int wB, int gS, int xB) {
    const int tid = threadIdx.x;
    const int bid = blockIdx.x;

    // ---------------- phase A1: per-molecule prep ----------------
    if (bid < molB) {
        __shared__ float k_s[16][F_DIM];
        __shared__ float e_s[16][2], en_s[16][2];
        __shared__ float red[8];
        int b0 = bid * 16;

        if (tid < 16) {
            int mol = b0 + tid;
            float Ev = (mol < B) ? E[mol] : 0.f;
            float e0 = fmaxf(Ev, 0.f), e1 = fmaxf(-Ev, 0.f);
            e_s[tid][0]  = e0;             e_s[tid][1]  = e1;
            en_s[tid][0] = fminf(e0, 1.f); en_s[tid][1] = fminf(e1, 1.f);
        }
        __syncthreads();

        float wk0 = Wk[tid * 2], wk1 = Wk[tid * 2 + 1];
        float wv0 = Wv[tid * 2], wv1 = Wv[tid * 2 + 1];
        #pragma unroll
        for (int b = 0; b < 16; b++) {
            float kv = en_s[b][0] * wk0 + en_s[b][1] * wk1;
            k_s[b][tid] = kv;
            int mol = b0 + b;
            if (mol < B) g_vmol[mol * F_DIM + tid] = e_s[b][0] * wv0 + e_s[b][1] * wv1;
        }
        __syncthreads();

        float acc[16];
        #pragma unroll
        for (int b = 0; b < 16; b++) acc[b] = 0.f;
        for (int f = 0; f < F_DIM; f++) {
            float w = Wq[f * F_DIM + tid];
            #pragma unroll
            for (int b = 0; b < 16; b++) acc[b] += k_s[b][f] * w;
        }
        #pragma unroll
        for (int b = 0; b < 16; b++) {
            int mol = b0 + b;
            if (mol < B) g_kq[mol * F_DIM + tid] = acc[b];
        }

        float bqv = bq[tid];
        int lane = tid & 31, wid = tid >> 5;
        for (int b = 0; b < 16; b++) {
            float v = k_s[b][tid] * bqv;
            #pragma unroll
            for (int o = 16; o > 0; o >>= 1) v += __shfl_down_sync(0xffffffffu, v, o);
            if (lane == 0) red[wid] = v;
            __syncthreads();
            if (tid == 0) {
                float s = 0.f;
                #pragma unroll
                for (int w = 0; w < 8; w++) s += red[w];
                int mol = b0 + b;
                if (mol < B) g_kb[mol] = s;
            }
            __syncthreads();
        }
        if (tid == 0) {
            __threadfence();
            int c = atomicAdd(&g_ctrA, 1);
            if (c == molB - 1) *(volatile int*)&g_flagA = 1;
        }
        return;
    }

    // ---------------- phase A2: weight tf32 rounding ----------------
    if (bid < molB + wB) {
        int i = (bid - molB) * 256 + tid;
        int total = (2 * R + 1) * F_DIM * F_DIM;
        if (i < total) {
            int slot = i >> 16, j = i & 65535;
            const float* src = (slot == 2 * R) ? (Wout + j)
                             : (((slot & 1) ? W2 : W1) + (size_t)(slot >> 1) * 65536 + j);
            g_Wt[i] = tf32r(*src);
        }
        return;
    }

    // ---------------- phase B: per-atom scores + global reduce ----------------
    if (bid < molB + wB + gS) {
        int sbid = bid - molB - wB;
        if (tid == 0) {
            while (*(volatile int*)&g_flagA == 0) __nanosleep(64);
            __threadfence();
        }
        __syncthreads();

        __shared__ float wsum[8];
        __shared__ int sdone;
        int lane = tid & 31, wid = tid >> 5;
        int n = sbid * 8 + wid;
        float a = 0.f;
        if (n < N) {
            int m = idx[n];
            const float* xr = x    + (size_t)n * F_DIM;
            const float* kq = g_kq + (size_t)m * F_DIM;
            float s = 0.f;
            #pragma unroll
            for (int j = 0; j < 8; j++) { int c = lane + j * 32; s += xr[c] * kq[c]; }
            #pragma unroll
            for (int o = 16; o > 0; o >>= 1) s += __shfl_down_sync(0xffffffffu, s, o);
            if (lane == 0) {
                float d = (s + g_kb[m]) * 0.0625f;
                a = fmaxf(d, 0.f) + log1pf(expf(-fabsf(d)));
                g_a[n] = a;
            }
        }
        if (lane == 0) wsum[wid] = a;
        __syncthreads();
        if (tid == 0) {
            float t = 0.f;
            #pragma unroll
            for (int w = 0; w < 8; w++) t += wsum[w];
            g_part[sbid] = t;
            __threadfence();
            int c = atomicAdd(&g_ctrB, 1);
            sdone = (c == gS - 1);
        }
        __syncthreads();
        if (sdone) {
            __shared__ float red[256];
            float s = 0.f;
            for (int i = tid; i < gS; i += 256) s += g_part[i];
            red[tid] = s;
            __syncthreads();
            for (int o = 128; o > 0; o >>= 1) {
                if (tid < o) red[tid] += red[tid + o];
                __syncthreads();
            }
            if (tid == 0) {
                g_inv[0] = 1.f / (red[0] + 1e-8f);
                __threadfence();
                *(volatile int*)&g_flagB = 1;
            }
        }
        return;
    }

    // ---------------- phase C: stage-0 A transform ----------------
    {
        int xbid = bid - molB - wB - gS;
        if (tid == 0) {
            while (*(volatile int*)&g_flagB == 0) __nanosleep(64);
            __threadfence();
        }
        __syncthreads();

        int lane = tid & 31, wid = tid >> 5;
        int n = xbid * 8 + wid;
        if (n < N) {
            int m = idx[n];
            float sc = g_a[n] * g_inv[0];
            const float* vp = g_vmol + (size_t)m * F_DIM;
            float* ap = g_A0 + (size_t)n * F_DIM;
            #pragma unroll
            for (int j = 0; j < 8; j++) {
                int col = lane + j * 32;
                ap[col] = swtf(sc * vp[col], a1[col], b1[col]);
            }
        }
        __syncthreads();
        if (tid == 0) {
            int c = atomicAdd(&g_ctrC, 1);
            if (c == xB - 1) {   // last block: reset gating state for graph replay
                g_ctrA = 0; g_ctrB = 0; g_ctrC = 0;
                *(volatile int*)&g_flagA = 0;
                *(volatile int*)&g_flagB = 0;
            }
        }
    }
}

// ============================================================
// K2: pure-MMA tf32 GEMM, 3-stage cp.async pipeline, 2 CTAs/SM.
// (byte-identical to R13 winner)
// ============================================================
#define BK 32
#define NCHUNK (F_DIM / BK)
#define PITCH 144
#define A_TILE (128 * PITCH)
#define B_TILE (128 * PITCH)
#define SSZ    (A_TILE + B_TILE)
#define SM_AL   0
#define SM_BE   1024
#define SM_RSC  2048
#define SM_RM   2560
#define ST0     3072
#define SM_TOTAL (ST0 + 3 * SSZ)           // 113664 (x2 CTAs = 227328)
#define SM_STAGE ST0
#define EPITCH 528

__global__ void __launch_bounds__(256, 2) gemm_tc(
    int slot, int abuf, const float* __restrict__ eal, const float* __restrict__ ebe,
    int eres, int ebase, int ewriteH, int eout,
    float* outp, const int* __restrict__ idx, int Nrows) {
    extern __shared__ char smem[];
    const uint32_t sb = smem_u32(smem);
    const int tid  = threadIdx.x;
    const int lane = tid & 31, wrp = tid >> 5;
    const int warpM = wrp >> 2, warpN = wrp & 3;   // 2 x 4
    const int m0 = blockIdx.x * 128;
    const int n0 = blockIdx.y * 128;

    float* sAl  = (float*)(smem + SM_AL);
    float* sBe  = (float*)(smem + SM_BE);
    float* sRsc = (float*)(smem + SM_RSC);
    int*   sRm  = (int*)  (smem + SM_RM);

    sAl[tid] = eal[tid];
    sBe[tid] = ebe[tid];
    {
        int r = tid >> 1;
        if ((tid & 1) == 0) {
            int grow = m0 + r;
            if (grow < Nrows) { sRsc[r] = g_a[grow] * g_inv[0]; sRm[r] = idx[grow]; }
            else              { sRsc[r] = 0.f; sRm[r] = 0; }
        }
    }

    const float* Ar = abuf ? g_A1 : g_A0;
    float*       Aw = abuf ? g_A0 : g_A1;
    const float* Bb = g_Wt + (size_t)slot * 65536 + (size_t)n0 * F_DIM;

    float acc[4][4][4];
    #pragma unroll
    for (int i = 0; i < 4; i++)
        #pragma unroll
        for (int j = 0; j < 4; j++)
            #pragma unroll
            for (int l = 0; l < 4; l++) acc[i][j][l] = 0.f;

    auto cpAB = [&](int c, int st) {
        const int k0 = c * BK;
        const uint32_t base = sb + ST0 + (uint32_t)st * SSZ;
        #pragma unroll
        for (int i = 0; i < 4; i++) {
            int t = tid + i * 256;
            int row = t >> 3, c16 = t & 7;
            const float* srcA = Ar + (size_t)(m0 + row) * F_DIM + k0 + c16 * 4;
            CP_ASYNC16(base + (uint32_t)row * PITCH + c16 * 16, srcA);
        }
        #pragma unroll
        for (int i = 0; i < 4; i++) {
            int t = tid + i * 256;
            int row = t >> 3, c16 = t & 7;
            const float* srcB = Bb + (size_t)row * F_DIM + k0 + c16 * 4;
            CP_ASYNC16(base + A_TILE + (uint32_t)row * PITCH + c16 * 16, srcB);
        }
        CP_COMMIT();
    };

    cpAB(0, 0);
    cpAB(1, 1);

    const int rowA  = (lane & 7) + ((lane >> 3) & 1) * 8;
    const int colA  = (lane >> 4) * 16;
    const int rowB  = (lane & 7) + ((lane >> 4) & 1) * 8;
    const int byteB = ((lane >> 3) & 1) * 16;
    const uint32_t aOff = (uint32_t)(warpM * 64 + rowA) * PITCH + colA;
    const uint32_t bOff = A_TILE + (uint32_t)(warpN * 32 + rowB) * PITCH + byteB;

    for (int c = 0; c < NCHUNK; c++) {
        if (c + 1 == NCHUNK) CP_WAIT0(); else CP_WAIT1();
        __syncthreads();

        const uint32_t base = sb + ST0 + (uint32_t)(c % 3) * SSZ;
        const uint32_t aB = base + aOff;
        const uint32_t bB = base + bOff;
        #pragma unroll
        for (int ks = 0; ks < 4; ks++) {
            uint32_t bf[4][2];
            #pragma unroll
            for (int ntp = 0; ntp < 2; ntp++) {
                uint32_t t4[4];
                LDSM_X4(t4, bB + ntp * (16 * PITCH) + ks * 32);
                bf[2*ntp][0]   = t4[0]; bf[2*ntp][1]   = t4[1];
                bf[2*ntp+1][0] = t4[2]; bf[2*ntp+1][1] = t4[3];
            }
            #pragma unroll
            for (int mt = 0; mt < 4; mt++) {
                uint32_t af[4];
                LDSM_X4(af, aB + mt * (16 * PITCH) + ks * 32);
                #pragma unroll
                for (int nt = 0; nt < 4; nt++)
                    MMA_TF32(acc[mt][nt], af, bf[nt]);
            }
        }
        if (c + 2 < NCHUNK) cpAB(c + 2, (c + 2) % 3);
    }
    __syncthreads();

    // ================= epilogue =================
    const int rbase = warpM * 64 + (lane >> 2);
    const int lcb   = warpN * 32 + (lane & 3) * 2;

    if (eout) {
        #pragma unroll
        for (int mt = 0; mt < 4; mt++)
            #pragma unroll
            for (int rh = 0; rh < 2; rh++) {
                int lr = rbase + mt * 16 + rh * 8;
                #pragma unroll
                for (int nt = 0; nt < 4; nt++) {
                    int lc = lcb + nt * 8;
                    *(float2*)(smem + SM_STAGE + lr * EPITCH + lc * 4)
                        = make_float2(acc[mt][nt][rh*2], acc[mt][nt][rh*2+1]);
                }
            }
        __syncthreads();
        #pragma unroll
        for (int i = 0; i < 32; i++) {
            int t = tid + i * 256;
            int row = t >> 6, cp = t & 63;
            int grow = m0 + row;
            if (grow < Nrows) {
                float2 v = *(float2*)(smem + SM_STAGE + row * EPITCH + cp * 8);
                *(float2*)(outp + (size_t)grow * F_DIM + n0 + cp * 2) = v;
            }
        }
        return;
    }

    #pragma unroll
    for (int mt = 0; mt < 4; mt++)
        #pragma unroll
        for (int rh = 0; rh < 2; rh++) {
            int lr = rbase + mt * 16 + rh * 8;
            int grow = m0 + lr;
            #pragma unroll
            for (int nt = 0; nt < 4; nt++) {
                int lc = lcb + nt * 8;
                int gcol = n0 + lc;
                float v0 = acc[mt][nt][rh*2], v1 = acc[mt][nt][rh*2+1];
                if (eres) {
                    if (ebase == 0) {
                        float sc = sRsc[lr];
                        const float* vp = g_vmol + (size_t)sRm[lr] * F_DIM + gcol;
                        v0 += sc * vp[0]; v1 += sc * vp[1];
                    } else {
                        float2 o = *(const float2*)(g_H + (size_t)grow * F_DIM + gcol);
                        v0 += o.x; v1 += o.y;
                    }
                    if (ewriteH && grow < Nrows)
                        *(float2*)(g_H + (size_t)grow * F_DIM + gcol) = make_float2(v0, v1);
                }
                float t0 = swtf(v0, sAl[gcol],     sBe[gcol]);
                float t1 = swtf(v1, sAl[gcol + 1], sBe[gcol + 1]);
                *(float2*)(smem + SM_STAGE + lr * EPITCH + lc * 4) = make_float2(t0, t1);
            }
        }
    __syncthreads();
    #pragma unroll
    for (int i = 0; i < 32; i++) {
        int t = tid + i * 256;
        int row = t >> 6, cp = t & 63;
        int grow = m0 + row;
        if (grow < Nrows) {
            float2 v = *(float2*)(smem + SM_STAGE + row * EPITCH + cp * 8);
            *(float2*)(Aw + (size_t)grow * F_DIM + n0 + cp * 2) = v;
        }
    }
}

// ============================================================
extern "C" void kernel_launch(void* const* d_in, const int* in_sizes, int n_in,
                              void* d_out, int out_size) {
    const float* x    = (const float*)d_in[0];
    const float* E    = (const float*)d_in[1];
    const int*   asi  = (const int*)  d_in[2];
    const float* Wq   = (const float*)d_in[3];
    const float* bq   = (const float*)d_in[4];
    const float* Wk   = (const float*)d_in[5];
    const float* Wv   = (const float*)d_in[6];
    const float* W1   = (const float*)d_in[7];
    const float* W2   = (const float*)d_in[8];
    const float* a1   = (const float*)d_in[9];
    const float* b1   = (const float*)d_in[10];
    const float* a2   = (const float*)d_in[11];
    const float* b2   = (const float*)d_in[12];
    const float* oa   = (const float*)d_in[13];
    const float* ob   = (const float*)d_in[14];
    const float* Wout = (const float*)d_in[15];

    int B = in_sizes[1];
    int N = in_sizes[2];
    int R = in_sizes[7] / (F_DIM * F_DIM);
    float* out = (float*)d_out;

    cudaFuncSetAttribute(gemm_tc, cudaFuncAttributeMaxDynamicSharedMemorySize, SM_TOTAL);

    int molB = (B + 15) / 16;
    int wB   = (2 * R + 1) * F_DIM;          // (2R+1)*65536/256
    int gS   = (N + 7) / 8;
    int xB   = (N + 7) / 8;
    frontend<<<molB + wB + gS + xB, 256>>>(E, Wq, bq, Wk, Wv, x, asi,
                                           W1, W2, Wout, a1, b1,
                                           B, N, R, molB, wB, gS, xB);   // launch 0

    dim3 grid((N + 127) / 128, 2);
    int abuf = 0;
    for (int i = 0; i < R; i++) {
        gemm_tc<<<grid, 256, SM_TOTAL>>>(2 * i, abuf, a2 + i * F_DIM, b2 + i * F_DIM,
                                         0, 0, 0, 0, out, asi, N);
        abuf ^= 1;
        const float* nal = (i + 1 < R) ? (a1 + (i + 1) * F_DIM) : oa;
        const float* nbe = (i + 1 < R) ? (b1 + (i + 1) * F_DIM) : ob;
        gemm_tc<<<grid, 256, SM_TOTAL>>>(2 * i + 1, abuf, nal, nbe,
                                         1, (i == 0) ? 0 : 1, (i < R - 1) ? 1 : 0, 0,
                                         out, asi, N);
        abuf ^= 1;
    }
    gemm_tc<<<grid, 256, SM_TOTAL>>>(2 * R, abuf, oa, ob, 0, 0, 0, 1, out, asi, N);
}

// round 17
// speedup vs baseline: 1.0590x; 1.0590x over previous
#include <cuda_runtime.h>
#include <cuda_bf16.h>
#include <math.h>
#include <stdint.h>

#define F_DIM 256
#define N_MAX 200000
#define B_MAX 4000
#define NPAD (N_MAX + 128)

// ---- scratch (device globals: allocation-free) ----
__device__ float g_kq[B_MAX * F_DIM];
__device__ float g_kb[B_MAX];
__device__ float g_vmol[B_MAX * F_DIM];
__device__ float g_a[N_MAX];
__device__ float g_part[(N_MAX + 7) / 8];
__device__ float g_inv[1];
__device__ int   g_ctr;
__device__ float g_H[(size_t)NPAD * F_DIM];
// ping-pong tf32 A operand buffers (stage parity)
__device__ float g_A0[(size_t)NPAD * F_DIM];
__device__ float g_A1[(size_t)NPAD * F_DIM];
__device__ float g_Wt[5 * F_DIM * F_DIM];   // tf32-rounded weights

// ============================================================
// helpers
// ============================================================
__device__ __forceinline__ uint32_t smem_u32(const void* p) {
    uint32_t a;
    asm("{ .reg .u64 t; cvta.to.shared.u64 t, %1; cvt.u32.u64 %0, t; }" : "=r"(a) : "l"(p));
    return a;
}
#define LDSM_X4(r, addr) \
    asm volatile("ldmatrix.sync.aligned.m8n8.x4.shared.b16 {%0,%1,%2,%3}, [%4];" \
        : "=r"((r)[0]), "=r"((r)[1]), "=r"((r)[2]), "=r"((r)[3]) : "r"(addr))
#define MMA_TF32(c, a, b) \
    asm volatile("mma.sync.aligned.m16n8k8.row.col.f32.tf32.tf32.f32 " \
        "{%0,%1,%2,%3}, {%4,%5,%6,%7}, {%8,%9}, {%0,%1,%2,%3};" \
        : "+f"((c)[0]), "+f"((c)[1]), "+f"((c)[2]), "+f"((c)[3]) \
        : "r"((a)[0]), "r"((a)[1]), "r"((a)[2]), "r"((a)[3]), "r"((b)[0]), "r"((b)[1]))
#define CP_ASYNC16(dst, src) \
    asm volatile("cp.async.cg.shared.global [%0], [%1], 16;" :: "r"(dst), "l"(src))
#define CP_COMMIT() asm volatile("cp.async.commit_group;" ::: "memory")
#define CP_WAIT0()  asm volatile("cp.async.wait_group 0;" ::: "memory")
#define CP_WAIT1()  asm volatile("cp.async.wait_group 1;" ::: "memory")

__device__ __forceinline__ float tf32r(float x) {
    uint32_t u;
    asm("cvt.rna.tf32.f32 %0, %1;" : "=r"(u) : "f"(x));
    return __uint_as_float(u);
}
__device__ __forceinline__ float swtf(float v, float al, float be) {
    float s  = be * v;
    float sw = al * s * (1.f / (1.f + __expf(-s)));
    return tf32r(sw);
}

// ============================================================
// K1: per-molecule prep
// ============================================================
__global__ void mol_prep(const float* __restrict__ E, const float* __restrict__ Wq,
                         const float* __restrict__ bq, const float* __restrict__ Wk,
                         const float* __restrict__ Wv, int B) {
    __shared__ float k_s[16][F_DIM];
    __shared__ float e_s[16][2], en_s[16][2];
    __shared__ float red[8];
    int tid = threadIdx.x;
    int b0  = blockIdx.x * 16;

    if (tid < 16) {
        int mol = b0 + tid;
        float Ev = (mol < B) ? E[mol] : 0.f;
        float e0 = fmaxf(Ev, 0.f), e1 = fmaxf(-Ev, 0.f);
        e_s[tid][0]  = e0;             e_s[tid][1]  = e1;
        en_s[tid][0] = fminf(e0, 1.f); en_s[tid][1] = fminf(e1, 1.f);
    }
    __syncthreads();

    float wk0 = Wk[tid * 2], wk1 = Wk[tid * 2 + 1];
    float wv0 = Wv[tid * 2], wv1 = Wv[tid * 2 + 1];
    #pragma unroll
    for (int b = 0; b < 16; b++) {
        float kv = en_s[b][0] * wk0 + en_s[b][1] * wk1;
        k_s[b][tid] = kv;
        int mol = b0 + b;
        if (mol < B) g_vmol[mol * F_DIM + tid] = e_s[b][0] * wv0 + e_s[b][1] * wv1;
    }
    __syncthreads();

    float acc[16];
    #pragma unroll
    for (int b = 0; b < 16; b++) acc[b] = 0.f;
    for (int f = 0; f < F_DIM; f++) {
        float w = Wq[f * F_DIM + tid];
        #pragma unroll
        for (int b = 0; b < 16; b++) acc[b] += k_s[b][f] * w;
    }
    #pragma unroll
    for (int b = 0; b < 16; b++) {
        int mol = b0 + b;
        if (mol < B) g_kq[mol * F_DIM + tid] = acc[b];
    }

    float bqv = bq[tid];
    int lane = tid & 31, wid = tid >> 5;
    for (int b = 0; b < 16; b++) {
        float v = k_s[b][tid] * bqv;
        #pragma unroll
        for (int o = 16; o > 0; o >>= 1) v += __shfl_down_sync(0xffffffffu, v, o);
        if (lane == 0) red[wid] = v;
        __syncthreads();
        if (tid == 0) {
            float s = 0.f;
            #pragma unroll
            for (int w = 0; w < 8; w++) s += red[w];
            int mol = b0 + b;
            if (mol < B) g_kb[mol] = s;
        }
        __syncthreads();
    }
}

// ============================================================
// K2: per-atom score + fused last-block global reduction -> g_inv
// ============================================================
__global__ void atom_score(const float* __restrict__ x, const int* __restrict__ idx, int N) {
    __shared__ float wsum[8];
    __shared__ int sdone;
    int tid = threadIdx.x, lane = tid & 31, wid = tid >> 5;
    int n = blockIdx.x * 8 + wid;
    float a = 0.f;
    if (n < N) {
        int m = idx[n];
        const float* xr = x    + (size_t)n * F_DIM;
        const float* kq = g_kq + (size_t)m * F_DIM;
        float s = 0.f;
        #pragma unroll
        for (int j = 0; j < 8; j++) { int c = lane + j * 32; s += xr[c] * kq[c]; }
        #pragma unroll
        for (int o = 16; o > 0; o >>= 1) s += __shfl_down_sync(0xffffffffu, s, o);
        if (lane == 0) {
            float d = (s + g_kb[m]) * 0.0625f;
            a = fmaxf(d, 0.f) + log1pf(expf(-fabsf(d)));
            g_a[n] = a;
        }
    }
    if (lane == 0) wsum[wid] = a;
    __syncthreads();
    if (tid == 0) {
        float t = 0.f;
        #pragma unroll
        for (int w = 0; w < 8; w++) t += wsum[w];
        g_part[blockIdx.x] = t;
        __threadfence();
        int c = atomicAdd(&g_ctr, 1);
        sdone = (c == (int)gridDim.x - 1);
    }
    __syncthreads();
    if (sdone) {
        __shared__ float red[256];
        float s = 0.f;
        int nparts = gridDim.x;
        for (int i = tid; i < nparts; i += 256) s += g_part[i];
        red[tid] = s;
        __syncthreads();
        for (int o = 128; o > 0; o >>= 1) {
            if (tid < o) red[tid] += red[tid + o];
            __syncthreads();
        }
        if (tid == 0) { g_inv[0] = 1.f / (red[0] + 1e-8f); g_ctr = 0; }
    }
}

// ============================================================
// K3: weight tf32-round + stage-0 A transform (into buffer 0)
// ============================================================
__global__ void prep_misc(const float* __restrict__ W1, const float* __restrict__ W2,
                          const float* __restrict__ Wout,
                          const float* __restrict__ a1, const float* __restrict__ b1,
                          const int* __restrict__ idx, int R, int wblocks, int N) {
    int tid = threadIdx.x;
    if ((int)blockIdx.x < wblocks) {
        int i = blockIdx.x * 256 + tid;
        int total = (2 * R + 1) * F_DIM * F_DIM;
        if (i >= total) return;
        int slot = i >> 16, j = i & 65535;
        const float* src = (slot == 2 * R) ? (Wout + j)
                         : (((slot & 1) ? W2 : W1) + (size_t)(slot >> 1) * 65536 + j);
        g_Wt[i] = tf32r(*src);
        return;
    }
    int xb  = blockIdx.x - wblocks;
    int wid = tid >> 5, lane = tid & 31;
    int n = xb * 8 + wid;
    if (n >= N) return;
    int m = idx[n];
    float sc = g_a[n] * g_inv[0];
    const float* vp = g_vmol + (size_t)m * F_DIM;
    float* ap = g_A0 + (size_t)n * F_DIM;
    #pragma unroll
    for (int j = 0; j < 8; j++) {
        int col = lane + j * 32;
        ap[col] = swtf(sc * vp[col], a1[col], b1[col]);
    }
}

// ============================================================
// K4: pure-MMA tf32 GEMM, 3-stage cp.async pipeline, 2 CTAs/SM.
// Mainloop fully unrolled: stage indices & k-offsets are compile-time,
// gmem pointers are induction variables -> minimal ALU in hot loop.
// ============================================================
#define BK 32
#define NCHUNK (F_DIM / BK)
#define PITCH 144
#define A_TILE (128 * PITCH)
#define B_TILE (128 * PITCH)
#define SSZ    (A_TILE + B_TILE)
#define SM_AL   0
#define SM_BE   1024
#define SM_RSC  2048
#define SM_RM   2560
#define ST0     3072
#define SM_TOTAL (ST0 + 3 * SSZ)           // 113664 (x2 CTAs = 227328)
#define SM_STAGE ST0
#define EPITCH 528

__global__ void __launch_bounds__(256, 2) gemm_tc(
    int slot, int abuf, const float* __restrict__ eal, const float* __restrict__ ebe,
    int eres, int ebase, int ewriteH, int eout,
    float* outp, const int* __restrict__ idx, int Nrows) {
    extern __shared__ char smem[];
    const uint32_t sb = smem_u32(smem);
    const int tid  = threadIdx.x;
    const int lane = tid & 31, wrp = tid >> 5;
    const int warpM = wrp >> 2, warpN = wrp & 3;   // 2 x 4
    const int m0 = blockIdx.x * 128;
    const int n0 = blockIdx.y * 128;

    float* sAl  = (float*)(smem + SM_AL);
    float* sBe  = (float*)(smem + SM_BE);
    float* sRsc = (float*)(smem + SM_RSC);
    int*   sRm  = (int*)  (smem + SM_RM);

    sAl[tid] = eal[tid];
    sBe[tid] = ebe[tid];
    if (eres && ebase == 0) {            // gather metadata only when used
        int r = tid >> 1;
        if ((tid & 1) == 0) {
            int grow = m0 + r;
            if (grow < Nrows) { sRsc[r] = g_a[grow] * g_inv[0]; sRm[r] = idx[grow]; }
            else              { sRsc[r] = 0.f; sRm[r] = 0; }
        }
    }

    const float* Ar = abuf ? g_A1 : g_A0;
    float*       Aw = abuf ? g_A0 : g_A1;
    const float* Bb = g_Wt + (size_t)slot * 65536 + (size_t)n0 * F_DIM;

    float acc[4][4][4];
    #pragma unroll
    for (int i = 0; i < 4; i++)
        #pragma unroll
        for (int j = 0; j < 4; j++)
            #pragma unroll
            for (int l = 0; l < 4; l++) acc[i][j][l] = 0.f;

    // per-thread gmem induction pointers (advance by BK floats per chunk)
    const int ldrow = tid >> 3, ldc16 = tid & 7;
    const float* pA = Ar + (size_t)(m0 + ldrow) * F_DIM + ldc16 * 4;
    const float* pB = Bb + (size_t)ldrow * F_DIM + ldc16 * 4;
    const uint32_t dA = sb + ST0 + (uint32_t)ldrow * PITCH + ldc16 * 16;
    const uint32_t dB = dA + A_TILE;

    auto cpAB = [&](int c, int st) {
        const uint32_t so = (uint32_t)st * SSZ;
        const int go = c * BK;
        #pragma unroll
        for (int i = 0; i < 4; i++)
            CP_ASYNC16(dA + so + i * (32 * PITCH), pA + (size_t)(i * 32) * F_DIM + go);
        #pragma unroll
        for (int i = 0; i < 4; i++)
            CP_ASYNC16(dB + so + i * (32 * PITCH), pB + (size_t)(i * 32) * F_DIM + go);
        CP_COMMIT();
    };

    cpAB(0, 0);
    cpAB(1, 1);

    const int rowA  = (lane & 7) + ((lane >> 3) & 1) * 8;
    const int colA  = (lane >> 4) * 16;
    const int rowB  = (lane & 7) + ((lane >> 4) & 1) * 8;
    const int byteB = ((lane >> 3) & 1) * 16;
    const uint32_t aOff = sb + ST0 + (uint32_t)(warpM * 64 + rowA) * PITCH + colA;
    const uint32_t bOff = sb + ST0 + A_TILE + (uint32_t)(warpN * 32 + rowB) * PITCH + byteB;

    #pragma unroll
    for (int c = 0; c < NCHUNK; c++) {
        if (c + 1 == NCHUNK) { CP_WAIT0(); } else { CP_WAIT1(); }
        __syncthreads();

        const uint32_t so = (uint32_t)((c % 3) * SSZ);   // compile-time (unrolled)
        const uint32_t aB = aOff + so;
        const uint32_t bB = bOff + so;
        #pragma unroll
        for (int ks = 0; ks < 4; ks++) {
            uint32_t bf[4][2];
            #pragma unroll
            for (int ntp = 0; ntp < 2; ntp++) {
                uint32_t t4[4];
                LDSM_X4(t4, bB + ntp * (16 * PITCH) + ks * 32);
                bf[2*ntp][0]   = t4[0]; bf[2*ntp][1]   = t4[1];
                bf[2*ntp+1][0] = t4[2]; bf[2*ntp+1][1] = t4[3];
            }
            #pragma unroll
            for (int mt = 0; mt < 4; mt++) {
                uint32_t af[4];
                LDSM_X4(af, aB + mt * (16 * PITCH) + ks * 32);
                #pragma unroll
                for (int nt = 0; nt < 4; nt++)
                    MMA_TF32(acc[mt][nt], af, bf[nt]);
            }
        }
        if (c + 2 < NCHUNK) cpAB(c + 2, (c + 2) % 3);
    }
    __syncthreads();

    // ================= epilogue =================
    const int rbase = warpM * 64 + (lane >> 2);
    const int lcb   = warpN * 32 + (lane & 3) * 2;

    if (eout) {
        #pragma unroll
        for (int mt = 0; mt < 4; mt++)
            #pragma unroll
            for (int rh = 0; rh < 2; rh++) {
                int lr = rbase + mt * 16 + rh * 8;
                #pragma unroll
                for (int nt = 0; nt < 4; nt++) {
                    int lc = lcb + nt * 8;
                    *(float2*)(smem + SM_STAGE + lr * EPITCH + lc * 4)
                        = make_float2(acc[mt][nt][rh*2], acc[mt][nt][rh*2+1]);
                }
            }
        __syncthreads();
        #pragma unroll
        for (int i = 0; i < 32; i++) {
            int t = tid + i * 256;
            int row = t >> 6, cp = t & 63;
            int grow = m0 + row;
            if (grow < Nrows) {
                float2 v = *(float2*)(smem + SM_STAGE + row * EPITCH + cp * 8);
                *(float2*)(outp + (size_t)grow * F_DIM + n0 + cp * 2) = v;
            }
        }
        return;
    }

    #pragma unroll
    for (int mt = 0; mt < 4; mt++)
        #pragma unroll
        for (int rh = 0; rh < 2; rh++) {
            int lr = rbase + mt * 16 + rh * 8;
            int grow = m0 + lr;
            #pragma unroll
            for (int nt = 0; nt < 4; nt++) {
                int lc = lcb + nt * 8;
                int gcol = n0 + lc;
                float v0 = acc[mt][nt][rh*2], v1 = acc[mt][nt][rh*2+1];
                if (eres) {
                    if (ebase == 0) {
                        float sc = sRsc[lr];
                        const float* vp = g_vmol + (size_t)sRm[lr] * F_DIM + gcol;
                        v0 += sc * vp[0]; v1 += sc * vp[1];
                    } else {
                        float2 o = *(const float2*)(g_H + (size_t)grow * F_DIM + gcol);
                        v0 += o.x; v1 += o.y;
                    }
                    if (ewriteH && grow < Nrows)
                        *(float2*)(g_H + (size_t)grow * F_DIM + gcol) = make_float2(v0, v1);
                }
                float t0 = swtf(v0, sAl[gcol],     sBe[gcol]);
                float t1 = swtf(v1, sAl[gcol + 1], sBe[gcol + 1]);
                *(float2*)(smem + SM_STAGE + lr * EPITCH + lc * 4) = make_float2(t0, t1);
            }
        }
    __syncthreads();
    #pragma unroll
    for (int i = 0; i < 32; i++) {
        int t = tid + i * 256;
        int row = t >> 6, cp = t & 63;
        int grow = m0 + row;
        if (grow < Nrows) {
            float2 v = *(float2*)(smem + SM_STAGE + row * EPITCH + cp * 8);
            *(float2*)(Aw + (size_t)grow * F_DIM + n0 + cp * 2) = v;
        }
    }
}

// ============================================================
extern "C" void kernel_launch(void* const* d_in, const int* in_sizes, int n_in,
                              void* d_out, int out_size) {
    const float* x    = (const float*)d_in[0];
    const float* E    = (const float*)d_in[1];
    const int*   asi  = (const int*)  d_in[2];
    const float* Wq   = (const float*)d_in[3];
    const float* bq   = (const float*)d_in[4];
    const float* Wk   = (const float*)d_in[5];
    const float* Wv   = (const float*)d_in[6];
    const float* W1   = (const float*)d_in[7];
    const float* W2   = (const float*)d_in[8];
    const float* a1   = (const float*)d_in[9];
    const float* b1   = (const float*)d_in[10];
    const float* a2   = (const float*)d_in[11];
    const float* b2   = (const float*)d_in[12];
    const float* oa   = (const float*)d_in[13];
    const float* ob   = (const float*)d_in[14];
    const float* Wout = (const float*)d_in[15];

    int B = in_sizes[1];
    int N = in_sizes[2];
    int R = in_sizes[7] / (F_DIM * F_DIM);
    float* out = (float*)d_out;

    cudaFuncSetAttribute(gemm_tc, cudaFuncAttributeMaxDynamicSharedMemorySize, SM_TOTAL);

    mol_prep<<<(B + 15) / 16, 256>>>(E, Wq, bq, Wk, Wv, B);              // 0

    int gS = (N + 7) / 8;
    atom_score<<<gS, 256>>>(x, asi, N);                                   // 1

    int wblocks = (2 * R + 1) * F_DIM;
    int xblocks = (N + 7) / 8;
    prep_misc<<<wblocks + xblocks, 256>>>(W1, W2, Wout, a1, b1, asi, R, wblocks, N);  // 2

    dim3 grid((N + 127) / 128, 2);
    int abuf = 0;
    for (int i = 0; i < R; i++) {
        gemm_tc<<<grid, 256, SM_TOTAL>>>(2 * i, abuf, a2 + i * F_DIM, b2 + i * F_DIM,
                                         0, 0, 0, 0, out, asi, N);
        abuf ^= 1;
        const float* nal = (i + 1 < R) ? (a1 + (i + 1) * F_DIM) : oa;
        const float* nbe = (i + 1 < R) ? (b1 + (i + 1) * F_DIM) : ob;
        gemm_tc<<<grid, 256, SM_TOTAL>>>(2 * i + 1, abuf, nal, nbe,
                                         1, (i == 0) ? 0 : 1, (i < R - 1) ? 1 : 0, 0,
                                         out, asi, N);
        abuf ^= 1;
    }
    gemm_tc<<<grid, 256, SM_TOTAL>>>(2 * R, abuf, oa, ob, 0, 0, 0, 1, out, asi, N);
}